// round 12
// baseline (speedup 1.0000x reference)
#include <cuda_runtime.h>
#include <cuda_bf16.h>
#include <cstdint>

#define N_NODES_MAX 100000
#define FEAT 16

__device__ int   g_deg[N_NODES_MAX];   // zero at load; every call re-zeros it in compute_y
__device__ float g_y[N_NODES_MAX * FEAT];

// ---------------------------------------------------------------------------
// Kernel 1: degree histogram, 1 edge per thread. Maximizes the number of
// concurrent fire-and-forget REDG atomics in the LTS queues (the bound);
// the extra scalar loads are free (DRAM was at 8%).
// ---------------------------------------------------------------------------
__global__ void hist_kernel(const int* __restrict__ src, int E) {
    int i = blockIdx.x * blockDim.x + threadIdx.x;
    if (i < E) {
        atomicAdd(&g_deg[src[i]], 1);
    }
}

// ---------------------------------------------------------------------------
// Kernel 2: per-node precompute  y[n] = (deg[n]-1)*x[n] + extra[n],
// and reset g_deg[n] = 0 for the next call. The 4 chunk-threads of a node
// form an aligned quad in one warp: read deg, __syncwarp, quad leader zeros.
// ---------------------------------------------------------------------------
__global__ void compute_y_kernel(const float4* __restrict__ x4,
                                 const float4* __restrict__ e4,
                                 int n4) {
    int i = blockIdx.x * blockDim.x + threadIdx.x;
    if (i < n4) {
        int node = i >> 2;
        int d = g_deg[node];
        __syncwarp();
        if ((i & 3) == 0) g_deg[node] = 0;
        float s = (float)(d - 1);
        float4 xv = x4[i];
        float4 ev = e4[i];
        float4 y;
        y.x = fmaf(s, xv.x, ev.x);
        y.y = fmaf(s, xv.y, ev.y);
        y.z = fmaf(s, xv.z, ev.z);
        y.w = fmaf(s, xv.w, ev.w);
        reinterpret_cast<float4*>(g_y)[i] = y;
    }
}

// ---------------------------------------------------------------------------
// Kernel 3: edge gather, ILP=4 (R3's proven form: 28 regs, no spill).
// Thread t owns elements {t + k*Q : k=0..3}, Q = total/4. 4 src loads ->
// 4 gather LDG.128 -> 4 STG.128, all coalesced.
// ---------------------------------------------------------------------------
__global__ void gather_kernel(const int* __restrict__ src,
                              float4* __restrict__ out4,
                              int Q /* = E*4/4 = E */) {
    int t = blockIdx.x * blockDim.x + threadIdx.x;
    if (t < Q) {
        const float4* __restrict__ y4 = reinterpret_cast<const float4*>(g_y);

        int i0 = t;
        int i1 = t + Q;
        int i2 = t + 2 * Q;
        int i3 = t + 3 * Q;
        int s0 = __ldg(&src[i0 >> 2]);
        int s1 = __ldg(&src[i1 >> 2]);
        int s2 = __ldg(&src[i2 >> 2]);
        int s3 = __ldg(&src[i3 >> 2]);

        float4 v0 = __ldg(&y4[s0 * 4 + (i0 & 3)]);
        float4 v1 = __ldg(&y4[s1 * 4 + (i1 & 3)]);
        float4 v2 = __ldg(&y4[s2 * 4 + (i2 & 3)]);
        float4 v3 = __ldg(&y4[s3 * 4 + (i3 & 3)]);

        out4[i0] = v0;
        out4[i1] = v1;
        out4[i2] = v2;
        out4[i3] = v3;
    }
}

// ---------------------------------------------------------------------------
extern "C" void kernel_launch(void* const* d_in, const int* in_sizes, int n_in,
                              void* d_out, int out_size) {
    const float* x     = (const float*)d_in[0];       // [N, 16] f32
    const float* extra = (const float*)d_in[1];       // [N, 16] f32
    const int* edge_index = (const int*)d_in[2];      // [2, E] int32 row-major

    int N = in_sizes[0] / FEAT;
    int E = in_sizes[2] / 2;
    const int* src = edge_index;                      // row 0 = edge_index[0]

    const int B = 256;

    // 1) histogram: 1 edge/thread -> max outstanding atomics
    hist_kernel<<<(E + B - 1) / B, B>>>(src, E);

    // 2) per-node y = (deg-1)*x + extra, and reset deg for next call
    int n4 = N * (FEAT / 4);
    compute_y_kernel<<<(n4 + B - 1) / B, B>>>(
        (const float4*)x, (const float4*)extra, n4);

    // 3) gather: total = E*4 float4 elements, ILP=4 -> Q = E threads
    int Q = E;
    gather_kernel<<<(Q + B - 1) / B, B>>>(src, (float4*)d_out, Q);
}